// round 5
// baseline (speedup 1.0000x reference)
#include <cuda_runtime.h>
#include <cuda_bf16.h>
#include <math.h>
#include <cstdint>

#define B_ 64
#define C_ 273
#define T_ 2048
#define O_ 256
#define D_ 2048
#define MTOT (B_*C_)      /* 17472 */
#define NPAD 17536        /* 137*128 */
#define CPAD 288

// ---------------- scratch (static device globals; no allocation) ----------------
__device__ __align__(16) float g_hT[(size_t)D_ * O_];        // heads^T k-major [d][o], tf32
__device__ __align__(16) float g_S [(size_t)O_ * MTOT];      // scores [o][b*273+c]
__device__ __align__(16) float g_Wt[(size_t)B_ * CPAD * O_]; // weights^T [b][cpad][o], tf32

__device__ __forceinline__ unsigned f2tf(float x){
    unsigned u; asm("cvt.rna.tf32.f32 %0, %1;" : "=r"(u) : "f"(x)); return u;
}
__device__ __forceinline__ float f2tff(float x){ return __uint_as_float(f2tf(x)); }

__device__ __forceinline__ void cp_commit(){ asm volatile("cp.async.commit_group;\n"::); }
template<int N_> __device__ __forceinline__ void cp_wait(){ asm volatile("cp.async.wait_group %0;\n"::"n"(N_)); }
__device__ __forceinline__ void cpa16(float* dst, const float* src, bool pred){
    unsigned d = (unsigned)__cvta_generic_to_shared(dst);
    int sz = pred ? 16 : 0;
    asm volatile("cp.async.cg.shared.global [%0], [%1], 16, %2;\n" :: "r"(d), "l"(src), "r"(sz));
}
__device__ __forceinline__ void cpa16f(float* dst, const float* src){
    unsigned d = (unsigned)__cvta_generic_to_shared(dst);
    asm volatile("cp.async.cg.shared.global [%0], [%1], 16;\n" :: "r"(d), "l"(src));
}

// ---------------- transpose (+tf32 round): out[c][r] = round(in[r][c]) ----------------
__global__ void transpose_round_kernel(const float* __restrict__ in, float* __restrict__ out,
                                       int R, int Cc)
{
    __shared__ float t[32][33];
    int c0 = blockIdx.x*32, r0 = blockIdx.y*32;
    int tx = threadIdx.x, ty = threadIdx.y;  // 32 x 8
    #pragma unroll
    for (int i = 0; i < 4; i++){
        int r = r0 + ty + 8*i, c = c0 + tx;
        float v = (r < R && c < Cc) ? in[(long long)r*Cc + c] : 0.f;
        t[ty+8*i][tx] = f2tff(v);
    }
    __syncthreads();
    #pragma unroll
    for (int i = 0; i < 4; i++){
        int r = r0 + tx, c = c0 + ty + 8*i;
        if (c < Cc && r < R) out[(long long)c*R + r] = t[tx][ty+8*i];
    }
}

// =================================================================================
// GEMM1 (fused E-gen): S[m=o][n=bc] = sum_k heads[o][k] * E[bc][k]
// A = hT (K-major [k][o], tf32-rounded), B generated from sincos tables in smem.
// Block tile 128x128, BK=16, 256 threads (8 warps, 4x2 of 32x64), mma m16n8k8 tf32.
// =================================================================================
#define AP 136
#define G1_STAGES 4
#define G1_ASF (G1_STAGES*16*AP)   /* 8704 floats */
#define G1_BSF (2*16*AP)           /* 4352 floats */
#define TBLP 132
#define G1_TBLF (128*TBLP)         /* 16896 floats */
#define G1_SMEM ((G1_ASF + G1_BSF + G1_TBLF)*4)

__global__ void __launch_bounds__(256,1) gemm1_fused(
    const float* __restrict__ hT, const float* __restrict__ positions,
    float* __restrict__ S)
{
    extern __shared__ float sm[];
    float* As  = sm;
    float* Bs  = sm + G1_ASF;
    float* tbl = sm + G1_ASF + G1_BSF;

    int n0 = blockIdx.x*128, m0 = blockIdx.y*128;
    int tid  = threadIdx.x;
    int warp = tid >> 5, lane = tid & 31;
    int g = lane >> 2, tg = lane & 3;
    int wm = (warp >> 1) * 32;
    int wn = (warp & 1) * 64;

    // ---- build sincos tables: tbl[(dim*64 + {0:cos,32:sin} + i)*TBLP + n] ----
    const float twopi_w = 6.28318530717958647692f / 1.4f;
    #pragma unroll 1
    for (int u = 0; u < 32; u++){
        int id  = u*256 + tid;      // 0..8191 = 2 dims x 32 freqs x 128 cols
        int dim = id >> 12;
        int i   = (id >> 7) & 31;
        int n   = id & 127;
        int nn  = n0 + n;
        float c = 0.f, s = 0.f;
        if (nn < MTOT){
            float p = positions[2*nn + dim] + 0.2f;
            sincosf((float)i * (p * twopi_w), &s, &c);
        }
        tbl[(dim*64 +      i)*TBLP + n] = c;
        tbl[(dim*64 + 32 + i)*TBLP + n] = s;
    }

    // ---- A loader (cp.async), tile = 16 k-rows x 128 m ----
    auto loadA = [&](int st, int kt){
        int k0 = kt * 16;
        #pragma unroll
        for (int u = 0; u < 2; u++){
            int id = tid + 256*u;
            int r = id >> 5, cm = (id & 31) * 4;
            cpa16f(As + st*(16*AP) + r*AP + cm, hT + (long long)(k0+r)*O_ + m0 + cm);
        }
        cp_commit();
    };

    // ---- B generator: E[n][k] for k-tile kt into buffer bi ----
    auto genB = [&](int bi, int kt){
        int k0 = kt * 16;
        int r = tid >> 4, q = tid & 15;
        int k = k0 + r;
        int m = k & 1023;
        int i = m >> 5, j = m & 31;
        bool half = (k >= 1024);
        const float* cx = tbl + (      i)*TBLP;
        const float* sx = tbl + (32  + i)*TBLP;
        const float* cy = tbl + (64  + j)*TBLP;
        const float* sy = tbl + (96  + j)*TBLP;
        float* dst = Bs + bi*(16*AP) + r*AP;
        #pragma unroll
        for (int h = 0; h < 2; h++){
            int g4 = q*4 + h*64;
            float4 a = *(const float4*)(cx + g4);
            float4 b = *(const float4*)(sx + g4);
            float4 c = *(const float4*)(cy + g4);
            float4 d = *(const float4*)(sy + g4);
            float4 v;
            if (half){
                v.x = b.x*c.x + a.x*d.x; v.y = b.y*c.y + a.y*d.y;
                v.z = b.z*c.z + a.z*d.z; v.w = b.w*c.w + a.w*d.w;
            } else {
                v.x = a.x*c.x - b.x*d.x; v.y = a.y*c.y - b.y*d.y;
                v.z = a.z*c.z - b.z*d.z; v.w = a.w*c.w - b.w*d.w;
            }
            v.x = f2tff(v.x); v.y = f2tff(v.y); v.z = f2tff(v.z); v.w = f2tff(v.w);
            *(float4*)(dst + g4) = v;
        }
    };

    float acc[2][8][4];
    #pragma unroll
    for (int mt = 0; mt < 2; mt++)
        #pragma unroll
        for (int nt = 0; nt < 8; nt++)
            #pragma unroll
            for (int e = 0; e < 4; e++) acc[mt][nt][e] = 0.f;

    const int ktiles = D_ / 16;   // 128

    loadA(0, 0); loadA(1, 1); loadA(2, 2);
    __syncthreads();              // tables ready
    genB(0, 0);

    for (int kt = 0; kt < ktiles; kt++){
        cp_wait<G1_STAGES-2>();
        __syncthreads();          // A[kt] landed; B[kt&1] gen visible

        const float* dA = As + (kt % G1_STAGES)*(16*AP);
        const float* dB = Bs + (kt & 1)*(16*AP);

        #pragma unroll
        for (int ks = 0; ks < 2; ks++){
            int k0 = ks*8 + tg;
            float4 a0  = *(const float4*)(dA + (k0  )*AP + wm + 4*g);
            float4 a1  = *(const float4*)(dA + (k0+4)*AP + wm + 4*g);
            float4 b00 = *(const float4*)(dB + (k0  )*AP + wn + 8*g);
            float4 b01 = *(const float4*)(dB + (k0  )*AP + wn + 8*g + 4);
            float4 b10 = *(const float4*)(dB + (k0+4)*AP + wn + 8*g);
            float4 b11 = *(const float4*)(dB + (k0+4)*AP + wn + 8*g + 4);

            unsigned ua[2][4];
            ua[0][0]=__float_as_uint(a0.x); ua[1][0]=__float_as_uint(a0.y);
            ua[0][1]=__float_as_uint(a0.z); ua[1][1]=__float_as_uint(a0.w);
            ua[0][2]=__float_as_uint(a1.x); ua[1][2]=__float_as_uint(a1.y);
            ua[0][3]=__float_as_uint(a1.z); ua[1][3]=__float_as_uint(a1.w);

            unsigned ub[8][2];
            ub[0][0]=__float_as_uint(b00.x); ub[1][0]=__float_as_uint(b00.y);
            ub[2][0]=__float_as_uint(b00.z); ub[3][0]=__float_as_uint(b00.w);
            ub[4][0]=__float_as_uint(b01.x); ub[5][0]=__float_as_uint(b01.y);
            ub[6][0]=__float_as_uint(b01.z); ub[7][0]=__float_as_uint(b01.w);
            ub[0][1]=__float_as_uint(b10.x); ub[1][1]=__float_as_uint(b10.y);
            ub[2][1]=__float_as_uint(b10.z); ub[3][1]=__float_as_uint(b10.w);
            ub[4][1]=__float_as_uint(b11.x); ub[5][1]=__float_as_uint(b11.y);
            ub[6][1]=__float_as_uint(b11.z); ub[7][1]=__float_as_uint(b11.w);

            #pragma unroll
            for (int mt = 0; mt < 2; mt++)
                #pragma unroll
                for (int nt = 0; nt < 8; nt++){
                    asm volatile(
                        "mma.sync.aligned.m16n8k8.row.col.f32.tf32.tf32.f32 "
                        "{%0,%1,%2,%3}, {%4,%5,%6,%7}, {%8,%9}, {%0,%1,%2,%3};"
                        : "+f"(acc[mt][nt][0]), "+f"(acc[mt][nt][1]),
                          "+f"(acc[mt][nt][2]), "+f"(acc[mt][nt][3])
                        : "r"(ua[mt][0]), "r"(ua[mt][1]), "r"(ua[mt][2]), "r"(ua[mt][3]),
                          "r"(ub[nt][0]), "r"(ub[nt][1]));
                }
        }

        if (kt + G1_STAGES - 1 < ktiles) loadA((kt + G1_STAGES - 1) % G1_STAGES, kt + G1_STAGES - 1);
        else                             cp_commit();
        if (kt + 1 < ktiles)             genB((kt + 1) & 1, kt + 1);
    }

    // epilogue: thread owns rows {m0+wm+4g+2h+mt}, 16 contiguous cols at n0+wn+16tg
    int cb = n0 + wn + 16*tg;
    #pragma unroll
    for (int mt = 0; mt < 2; mt++){
        #pragma unroll
        for (int h = 0; h < 2; h++){
            int row = m0 + wm + 4*g + 2*h + mt;
            float* Cr = S + (long long)row*MTOT;
            float4 v0, v1, v2, v3;
            v0.x=acc[mt][0][2*h];   v0.y=acc[mt][1][2*h];   v0.z=acc[mt][2][2*h];   v0.w=acc[mt][3][2*h];
            v1.x=acc[mt][4][2*h];   v1.y=acc[mt][5][2*h];   v1.z=acc[mt][6][2*h];   v1.w=acc[mt][7][2*h];
            v2.x=acc[mt][0][2*h+1]; v2.y=acc[mt][1][2*h+1]; v2.z=acc[mt][2][2*h+1]; v2.w=acc[mt][3][2*h+1];
            v3.x=acc[mt][4][2*h+1]; v3.y=acc[mt][5][2*h+1]; v3.z=acc[mt][6][2*h+1]; v3.w=acc[mt][7][2*h+1];
            if (cb      < MTOT) *(float4*)(Cr + cb     ) = v0;
            if (cb + 4  < MTOT) *(float4*)(Cr + cb + 4 ) = v1;
            if (cb + 8  < MTOT) *(float4*)(Cr + cb + 8 ) = v2;
            if (cb + 12 < MTOT) *(float4*)(Cr + cb + 12) = v3;
        }
    }
}

// =================================================================================
// GEMM2: out[b][m=o][n=t] = sum_c Wt[b][c][o] * x[b][c][t]
// A = Wt (K-major, tf32, zero-padded to CPAD), B = x (K-major natural, CVT in-loop).
// 5-stage cp.async, same fragment scheme.
// =================================================================================
#define G2_STAGES 5
#define G2_STGF (2*16*AP)
#define G2_SMEM (G2_STAGES*G2_STGF*4)

__global__ void __launch_bounds__(256) gemm2_kernel(
    const float* __restrict__ Atg, const float* __restrict__ Bg, float* __restrict__ Cg)
{
    extern __shared__ float sm[];
    long long bz = blockIdx.z;
    const float* At = Atg + bz * (long long)CPAD*O_;
    const float* B  = Bg  + bz * (long long)C_*T_;
    float*       C  = Cg  + bz * (long long)O_*T_;

    int n0 = blockIdx.x * 128;
    int m0 = blockIdx.y * 128;
    int tid  = threadIdx.x;
    int warp = tid >> 5, lane = tid & 31;
    int g = lane >> 2, tg = lane & 3;
    int wm = (warp >> 1) * 32;
    int wn = (warp & 1) * 64;

    float acc[2][8][4];
    #pragma unroll
    for (int mt = 0; mt < 2; mt++)
        #pragma unroll
        for (int nt = 0; nt < 8; nt++)
            #pragma unroll
            for (int e = 0; e < 4; e++) acc[mt][nt][e] = 0.f;

    const int ktiles = CPAD / 16;   // 18

    auto load_stage = [&](int s, int kt){
        float* dA = sm + s * G2_STGF;
        float* dB = dA + 16*AP;
        int k0 = kt * 16;
        #pragma unroll
        for (int j = 0; j < 2; j++){
            int id = tid + 256*j;
            int r = id >> 5, cm = (id & 31) * 4;
            cpa16f(dA + r*AP + cm, At + (long long)(k0+r)*O_ + m0 + cm);
        }
        #pragma unroll
        for (int j = 0; j < 2; j++){
            int id = tid + 256*j;
            int r = id >> 5, cn = (id & 31) * 4;
            cpa16(dB + r*AP + cn, B + (long long)(k0+r)*T_ + n0 + cn, (k0+r) < C_);
        }
        cp_commit();
    };

    load_stage(0, 0); load_stage(1, 1); load_stage(2, 2); load_stage(3, 3);

    for (int kt = 0; kt < ktiles; kt++){
        cp_wait<G2_STAGES-2>();
        __syncthreads();
        if (kt + G2_STAGES - 1 < ktiles) load_stage((kt + G2_STAGES - 1) % G2_STAGES, kt + G2_STAGES - 1);
        else                             cp_commit();

        const float* dA = sm + (kt % G2_STAGES) * G2_STGF;
        const float* dB = dA + 16*AP;

        #pragma unroll
        for (int ks = 0; ks < 2; ks++){
            int k0 = ks*8 + tg;
            float4 a0  = *(const float4*)(dA + (k0  )*AP + wm + 4*g);
            float4 a1  = *(const float4*)(dA + (k0+4)*AP + wm + 4*g);
            float4 b00 = *(const float4*)(dB + (k0  )*AP + wn + 8*g);
            float4 b01 = *(const float4*)(dB + (k0  )*AP + wn + 8*g + 4);
            float4 b10 = *(const float4*)(dB + (k0+4)*AP + wn + 8*g);
            float4 b11 = *(const float4*)(dB + (k0+4)*AP + wn + 8*g + 4);

            unsigned ua[2][4];
            ua[0][0]=__float_as_uint(a0.x); ua[1][0]=__float_as_uint(a0.y);
            ua[0][1]=__float_as_uint(a0.z); ua[1][1]=__float_as_uint(a0.w);
            ua[0][2]=__float_as_uint(a1.x); ua[1][2]=__float_as_uint(a1.y);
            ua[0][3]=__float_as_uint(a1.z); ua[1][3]=__float_as_uint(a1.w);

            unsigned ub[8][2];
            ub[0][0]=f2tf(b00.x); ub[1][0]=f2tf(b00.y); ub[2][0]=f2tf(b00.z); ub[3][0]=f2tf(b00.w);
            ub[4][0]=f2tf(b01.x); ub[5][0]=f2tf(b01.y); ub[6][0]=f2tf(b01.z); ub[7][0]=f2tf(b01.w);
            ub[0][1]=f2tf(b10.x); ub[1][1]=f2tf(b10.y); ub[2][1]=f2tf(b10.z); ub[3][1]=f2tf(b10.w);
            ub[4][1]=f2tf(b11.x); ub[5][1]=f2tf(b11.y); ub[6][1]=f2tf(b11.z); ub[7][1]=f2tf(b11.w);

            #pragma unroll
            for (int mt = 0; mt < 2; mt++)
                #pragma unroll
                for (int nt = 0; nt < 8; nt++){
                    asm volatile(
                        "mma.sync.aligned.m16n8k8.row.col.f32.tf32.tf32.f32 "
                        "{%0,%1,%2,%3}, {%4,%5,%6,%7}, {%8,%9}, {%0,%1,%2,%3};"
                        : "+f"(acc[mt][nt][0]), "+f"(acc[mt][nt][1]),
                          "+f"(acc[mt][nt][2]), "+f"(acc[mt][nt][3])
                        : "r"(ua[mt][0]), "r"(ua[mt][1]), "r"(ua[mt][2]), "r"(ua[mt][3]),
                          "r"(ub[nt][0]), "r"(ub[nt][1]));
                }
        }
        __syncthreads();
    }

    int cb = n0 + wn + 16*tg;   // always < T_ (2048 multiple of 128)
    #pragma unroll
    for (int mt = 0; mt < 2; mt++){
        #pragma unroll
        for (int h = 0; h < 2; h++){
            int row = m0 + wm + 4*g + 2*h + mt;
            float* Cr = C + (long long)row*T_;
            float4 v0, v1, v2, v3;
            v0.x=acc[mt][0][2*h];   v0.y=acc[mt][1][2*h];   v0.z=acc[mt][2][2*h];   v0.w=acc[mt][3][2*h];
            v1.x=acc[mt][4][2*h];   v1.y=acc[mt][5][2*h];   v1.z=acc[mt][6][2*h];   v1.w=acc[mt][7][2*h];
            v2.x=acc[mt][0][2*h+1]; v2.y=acc[mt][1][2*h+1]; v2.z=acc[mt][2][2*h+1]; v2.w=acc[mt][3][2*h+1];
            v3.x=acc[mt][4][2*h+1]; v3.y=acc[mt][5][2*h+1]; v3.z=acc[mt][6][2*h+1]; v3.w=acc[mt][7][2*h+1];
            *(float4*)(Cr + cb     ) = v0;
            *(float4*)(Cr + cb + 4 ) = v1;
            *(float4*)(Cr + cb + 8 ) = v2;
            *(float4*)(Cr + cb + 12) = v3;
        }
    }
}

// ---------------- softmax over C, writing W^T directly ----------------
// Block = (32 heads o0..o0+31) x (1 batch). Warp w handles o = o0 + 4w + p.
#define WPITCH 277
__global__ void __launch_bounds__(256) softmaxT_kernel(
    const float* __restrict__ S, const unsigned char* __restrict__ mask,
    float* __restrict__ Wt)
{
    __shared__ float wsm[32*WPITCH];
    const float NEG_INF = __int_as_float(0xff800000);
    int o0 = blockIdx.x * 32;
    int b  = blockIdx.y;
    int tid = threadIdx.x, wid = tid >> 5, lane = tid & 31;
    const unsigned char* mrow = mask + (size_t)b * C_;

    #pragma unroll
    for (int p = 0; p < 4; p++){
        int o = 4*wid + p;
        const float* row = S + (size_t)(o0 + o) * MTOT + (size_t)b * C_;
        float v[9];
        float vmax = NEG_INF;
        #pragma unroll
        for (int it = 0; it < 9; it++){
            int c = lane + 32*it;
            float s = NEG_INF;
            if (c < C_) s = mrow[c] ? NEG_INF : row[c];
            v[it] = s;
            vmax = fmaxf(vmax, s);
        }
        #pragma unroll
        for (int off = 16; off; off >>= 1)
            vmax = fmaxf(vmax, __shfl_xor_sync(0xffffffffu, vmax, off));
        float e[9], sum = 0.f;
        #pragma unroll
        for (int it = 0; it < 9; it++){
            e[it] = __expf(v[it] - vmax);
            sum += e[it];
        }
        #pragma unroll
        for (int off = 16; off; off >>= 1)
            sum += __shfl_xor_sync(0xffffffffu, sum, off);
        float inv = 1.f / sum;
        #pragma unroll
        for (int it = 0; it < 9; it++){
            int c = lane + 32*it;
            if (c < C_) wsm[o*WPITCH + c] = f2tff(e[it] * inv);
        }
    }
    __syncthreads();

    // write-out: Wt[b][c][o0+lane], warp per c, coalesced 128B
    float* base = Wt + (size_t)b * CPAD * O_ + o0;
    for (int c = wid; c < CPAD; c += 8){
        float v = (c < C_) ? wsm[lane*WPITCH + c] : 0.f;
        base[(size_t)c * O_ + lane] = v;
    }
}

// ---------------- launcher ----------------
extern "C" void kernel_launch(void* const* d_in, const int* in_sizes, int n_in,
                              void* d_out, int out_size)
{
    const float* x = nullptr;
    const float* positions = nullptr;
    const unsigned char* mask = nullptr;
    const float* heads = nullptr;
    for (int i = 0; i < n_in; i++){
        long long s = in_sizes[i];
        if      (s == (long long)B_*C_*T_) x         = (const float*)d_in[i];
        else if (s == (long long)B_*C_*2 ) positions = (const float*)d_in[i];
        else if (s == (long long)B_*C_   ) mask      = (const unsigned char*)d_in[i];
        else if (s == (long long)O_*D_   ) heads     = (const float*)d_in[i];
    }

    float *pHT, *pS, *pWt;
    cudaGetSymbolAddress((void**)&pHT, g_hT);
    cudaGetSymbolAddress((void**)&pS,  g_S);
    cudaGetSymbolAddress((void**)&pWt, g_Wt);

    cudaFuncSetAttribute(gemm1_fused,  cudaFuncAttributeMaxDynamicSharedMemorySize, G1_SMEM);
    cudaFuncSetAttribute(gemm2_kernel, cudaFuncAttributeMaxDynamicSharedMemorySize, G2_SMEM);

    // 1) heads^T (tf32-rounded): [2048][256]
    transpose_round_kernel<<<dim3(D_/32, O_/32), dim3(32,8)>>>(heads, pHT, O_, D_);

    // 2) fused E-gen GEMM: scores[o][bc]  (M=256, N=17472, K=2048)
    gemm1_fused<<<dim3(NPAD/128, O_/128), 256, G1_SMEM>>>(pHT, positions, pS);

    // 3) softmax -> Wt [b][cpad][o] (tf32-rounded, zero-padded)
    softmaxT_kernel<<<dim3(O_/32, B_), 256>>>(pS, mask, pWt);

    // 4) out[b] = W[b] @ x[b]: M=256, N=2048, K=288 (273 real), batched over b
    gemm2_kernel<<<dim3(T_/128, O_/128, B_), 256, G2_SMEM>>>(pWt, x, (float*)d_out);
}

// round 6
// speedup vs baseline: 1.0620x; 1.0620x over previous
#include <cuda_runtime.h>
#include <cuda_bf16.h>
#include <math.h>
#include <cstdint>

#define B_ 64
#define C_ 273
#define T_ 2048
#define O_ 256
#define D_ 2048
#define NF 32
#define MARGIN_F 0.2f
#define MTOT (B_*C_)      /* 17472 */
#define NPAD 17536        /* 137*128 */
#define CPAD 288

// ---------------- scratch (static device globals; no allocation) ----------------
__device__ __align__(16) float g_ET[(size_t)D_ * NPAD];      // E^T k-major [k][bc]
__device__ __align__(16) float g_hT[(size_t)D_ * O_];        // heads^T k-major [d][o], tf32
__device__ __align__(16) float g_S [(size_t)O_ * MTOT];      // scores [o][b*273+c]
__device__ __align__(16) float g_Wt[(size_t)B_ * CPAD * O_]; // weights^T [b][cpad][o], tf32

__device__ __forceinline__ unsigned f2tf(float x){
    unsigned u; asm("cvt.rna.tf32.f32 %0, %1;" : "=r"(u) : "f"(x)); return u;
}
__device__ __forceinline__ float f2tff(float x){ return __uint_as_float(f2tf(x)); }

__device__ __forceinline__ void cp_commit(){ asm volatile("cp.async.commit_group;\n"::); }
template<int N_> __device__ __forceinline__ void cp_wait(){ asm volatile("cp.async.wait_group %0;\n"::"n"(N_)); }
__device__ __forceinline__ void cpa16(float* dst, const float* src, bool pred){
    unsigned d = (unsigned)__cvta_generic_to_shared(dst);
    int sz = pred ? 16 : 0;
    asm volatile("cp.async.cg.shared.global [%0], [%1], 16, %2;\n" :: "r"(d), "l"(src), "r"(sz));
}
__device__ __forceinline__ void cpa16f(float* dst, const float* src){
    unsigned d = (unsigned)__cvta_generic_to_shared(dst);
    asm volatile("cp.async.cg.shared.global [%0], [%1], 16;\n" :: "r"(d), "l"(src));
}

// ---------------- etgen: build E^T k-major (tf32-rounded); pad cols -> 0 ----------------
__global__ void etgen_kernel(const float* __restrict__ positions){
    __shared__ float tc[2][NF][NF];
    __shared__ float ts[2][NF][NF];
    int n0 = blockIdx.x * 32;
    int tid = threadIdx.x;           // 256 threads
    const float twopi_w = 6.28318530717958647692f / 1.4f;
    #pragma unroll
    for (int u = 0; u < 8; u++){
        int idx   = tid + 256*u;
        int which = idx >> 10;
        int rem   = idx & 1023;
        int i     = rem >> 5;
        int r     = rem & 31;
        int n     = n0 + r;
        float c = 0.f, s = 0.f;
        if (n < MTOT){
            float p = positions[2*n + which] + MARGIN_F;
            sincosf((float)i * (p * twopi_w), &s, &c);
        }
        tc[which][i][r] = c;
        ts[which][i][r] = s;
    }
    __syncthreads();
    int r  = tid & 31;
    int kb = tid >> 5;
    #pragma unroll 4
    for (int k = kb; k < D_; k += 8){
        int m = k & 1023;
        int i = m >> 5, j = m & 31;
        float cx = tc[0][i][r], sx = ts[0][i][r];
        float cy = tc[1][j][r], sy = ts[1][j][r];
        float v = (k < 1024) ? (cx*cy - sx*sy) : (sx*cy + cx*sy);
        g_ET[(size_t)k * NPAD + n0 + r] = f2tff(v);
    }
}

// ---------------- transpose (+tf32 round): out[c][r] = round(in[r][c]) ----------------
__global__ void transpose_round_kernel(const float* __restrict__ in, float* __restrict__ out,
                                       int R, int Cc)
{
    __shared__ float t[32][33];
    int c0 = blockIdx.x*32, r0 = blockIdx.y*32;
    int tx = threadIdx.x, ty = threadIdx.y;  // 32 x 8
    #pragma unroll
    for (int i = 0; i < 4; i++){
        int r = r0 + ty + 8*i, c = c0 + tx;
        float v = (r < R && c < Cc) ? in[(long long)r*Cc + c] : 0.f;
        t[ty+8*i][tx] = f2tff(v);
    }
    __syncthreads();
    #pragma unroll
    for (int i = 0; i < 4; i++){
        int r = r0 + tx, c = c0 + ty + 8*i;
        if (c < Cc && r < R) out[(long long)c*R + r] = t[tx][ty+8*i];
    }
}

// =================================================================================
// TN GEMM: C[M=256-grid][N] = sum_k At[k][m] * B[k][n]; At,B K-major.
// Block 128x128, BK=16, 128 threads = 4 warps (2x2) of 64x64 warp tiles.
// 5-stage cp.async ring; AP=132 padding (conflict-free for the 8g+4tg pattern).
// =================================================================================
#define STAGES 5
#define AP 132
#define STGF (2*16*AP)              /* 4224 floats per stage */
#define GSMEM (STAGES*STGF*4)       /* 84480 bytes */

template<bool CVTB>
__global__ void __launch_bounds__(128,2) gemm_tc(
    const float* __restrict__ Atg, const float* __restrict__ Bg, float* __restrict__ Cg,
    int N, int K, int Kb, int lda, int ldb, int ldc,
    long long sA, long long sB, long long sC)
{
    extern __shared__ float sm[];
    const float* At = Atg + blockIdx.z*sA;
    const float* B  = Bg  + blockIdx.z*sB;
    float*       C  = Cg  + blockIdx.z*sC;

    int n0 = blockIdx.x*128, m0 = blockIdx.y*128;
    int tid  = threadIdx.x;
    int warp = tid >> 5, lane = tid & 31;
    int g = lane >> 2, tg = lane & 3;
    int wm = (warp >> 1) * 64;
    int wn = (warp &  1) * 64;

    float acc[4][8][4];
    #pragma unroll
    for (int mt = 0; mt < 4; mt++)
        #pragma unroll
        for (int nt = 0; nt < 8; nt++)
            #pragma unroll
            for (int e = 0; e < 4; e++) acc[mt][nt][e] = 0.f;

    const int ktiles = K / 16;

    auto load_stage = [&](int s, int kt){
        float* dA = sm + s*STGF;
        float* dB = dA + 16*AP;
        int k0 = kt * 16;
        #pragma unroll
        for (int j = 0; j < 4; j++){
            int id = tid + 128*j;
            int r = id >> 5, cc = (id & 31) * 4;
            cpa16f(dA + r*AP + cc, At + (long long)(k0+r)*lda + m0 + cc);
        }
        #pragma unroll
        for (int j = 0; j < 4; j++){
            int id = tid + 128*j;
            int r = id >> 5, cc = (id & 31) * 4;
            cpa16(dB + r*AP + cc, B + (long long)(k0+r)*ldb + n0 + cc, (k0+r) < Kb);
        }
        cp_commit();
    };

    load_stage(0,0); load_stage(1,1); load_stage(2,2); load_stage(3,3);

    for (int kt = 0; kt < ktiles; kt++){
        cp_wait<STAGES-2>();
        __syncthreads();
        if (kt + STAGES - 1 < ktiles) load_stage((kt + STAGES - 1) % STAGES, kt + STAGES - 1);
        else                          cp_commit();

        const float* dA = sm + (kt % STAGES)*STGF;
        const float* dB = dA + 16*AP;

        #pragma unroll
        for (int ks = 0; ks < 2; ks++){
            int kk = ks*8 + tg;
            const float* pa = dA + kk*AP + wm + 8*g;
            float4 a0 = *(const float4*)(pa);
            float4 a1 = *(const float4*)(pa + 4);
            float4 a2 = *(const float4*)(pa + 4*AP);
            float4 a3 = *(const float4*)(pa + 4*AP + 4);
            const float* pb = dB + kk*AP + wn + 8*g;
            float4 b0 = *(const float4*)(pb);
            float4 b1 = *(const float4*)(pb + 4);
            float4 b2 = *(const float4*)(pb + 4*AP);
            float4 b3 = *(const float4*)(pb + 4*AP + 4);

            unsigned ua[4][4];
            ua[0][0]=__float_as_uint(a0.x); ua[1][0]=__float_as_uint(a0.y);
            ua[2][0]=__float_as_uint(a0.z); ua[3][0]=__float_as_uint(a0.w);
            ua[0][1]=__float_as_uint(a1.x); ua[1][1]=__float_as_uint(a1.y);
            ua[2][1]=__float_as_uint(a1.z); ua[3][1]=__float_as_uint(a1.w);
            ua[0][2]=__float_as_uint(a2.x); ua[1][2]=__float_as_uint(a2.y);
            ua[2][2]=__float_as_uint(a2.z); ua[3][2]=__float_as_uint(a2.w);
            ua[0][3]=__float_as_uint(a3.x); ua[1][3]=__float_as_uint(a3.y);
            ua[2][3]=__float_as_uint(a3.z); ua[3][3]=__float_as_uint(a3.w);

            unsigned ub[8][2];
            if (CVTB){
                ub[0][0]=f2tf(b0.x); ub[1][0]=f2tf(b0.y); ub[2][0]=f2tf(b0.z); ub[3][0]=f2tf(b0.w);
                ub[4][0]=f2tf(b1.x); ub[5][0]=f2tf(b1.y); ub[6][0]=f2tf(b1.z); ub[7][0]=f2tf(b1.w);
                ub[0][1]=f2tf(b2.x); ub[1][1]=f2tf(b2.y); ub[2][1]=f2tf(b2.z); ub[3][1]=f2tf(b2.w);
                ub[4][1]=f2tf(b3.x); ub[5][1]=f2tf(b3.y); ub[6][1]=f2tf(b3.z); ub[7][1]=f2tf(b3.w);
            } else {
                ub[0][0]=__float_as_uint(b0.x); ub[1][0]=__float_as_uint(b0.y);
                ub[2][0]=__float_as_uint(b0.z); ub[3][0]=__float_as_uint(b0.w);
                ub[4][0]=__float_as_uint(b1.x); ub[5][0]=__float_as_uint(b1.y);
                ub[6][0]=__float_as_uint(b1.z); ub[7][0]=__float_as_uint(b1.w);
                ub[0][1]=__float_as_uint(b2.x); ub[1][1]=__float_as_uint(b2.y);
                ub[2][1]=__float_as_uint(b2.z); ub[3][1]=__float_as_uint(b2.w);
                ub[4][1]=__float_as_uint(b3.x); ub[5][1]=__float_as_uint(b3.y);
                ub[6][1]=__float_as_uint(b3.z); ub[7][1]=__float_as_uint(b3.w);
            }

            #pragma unroll
            for (int mt = 0; mt < 4; mt++)
                #pragma unroll
                for (int nt = 0; nt < 8; nt++){
                    asm volatile(
                        "mma.sync.aligned.m16n8k8.row.col.f32.tf32.tf32.f32 "
                        "{%0,%1,%2,%3}, {%4,%5,%6,%7}, {%8,%9}, {%0,%1,%2,%3};"
                        : "+f"(acc[mt][nt][0]), "+f"(acc[mt][nt][1]),
                          "+f"(acc[mt][nt][2]), "+f"(acc[mt][nt][3])
                        : "r"(ua[mt][0]), "r"(ua[mt][1]), "r"(ua[mt][2]), "r"(ua[mt][3]),
                          "r"(ub[nt][0]), "r"(ub[nt][1]));
                }
        }
    }

    // epilogue: rows m0+wm+8g+4h+mt (< M always: M multiple of 128), 16 cols at cb
    int cb = n0 + wn + 16*tg;
    #pragma unroll
    for (int mt = 0; mt < 4; mt++){
        #pragma unroll
        for (int h = 0; h < 2; h++){
            int row = m0 + wm + 8*g + 4*h + mt;
            float* Cr = C + (long long)row*ldc;
            float4 v0, v1, v2, v3;
            v0.x=acc[mt][0][2*h];   v0.y=acc[mt][1][2*h];   v0.z=acc[mt][2][2*h];   v0.w=acc[mt][3][2*h];
            v1.x=acc[mt][4][2*h];   v1.y=acc[mt][5][2*h];   v1.z=acc[mt][6][2*h];   v1.w=acc[mt][7][2*h];
            v2.x=acc[mt][0][2*h+1]; v2.y=acc[mt][1][2*h+1]; v2.z=acc[mt][2][2*h+1]; v2.w=acc[mt][3][2*h+1];
            v3.x=acc[mt][4][2*h+1]; v3.y=acc[mt][5][2*h+1]; v3.z=acc[mt][6][2*h+1]; v3.w=acc[mt][7][2*h+1];
            if (cb      < N) *(float4*)(Cr + cb     ) = v0;
            if (cb + 4  < N) *(float4*)(Cr + cb + 4 ) = v1;
            if (cb + 8  < N) *(float4*)(Cr + cb + 8 ) = v2;
            if (cb + 12 < N) *(float4*)(Cr + cb + 12) = v3;
        }
    }
}

// ---------------- softmax over C, writing W^T directly ----------------
#define WPITCH 277
__global__ void __launch_bounds__(256) softmaxT_kernel(
    const float* __restrict__ S, const unsigned char* __restrict__ mask,
    float* __restrict__ Wt)
{
    __shared__ float wsm[32*WPITCH];
    const float NEG_INF = __int_as_float(0xff800000);
    int o0 = blockIdx.x * 32;
    int b  = blockIdx.y;
    int tid = threadIdx.x, wid = tid >> 5, lane = tid & 31;
    const unsigned char* mrow = mask + (size_t)b * C_;

    #pragma unroll
    for (int p = 0; p < 4; p++){
        int o = 4*wid + p;
        const float* row = S + (size_t)(o0 + o) * MTOT + (size_t)b * C_;
        float v[9];
        float vmax = NEG_INF;
        #pragma unroll
        for (int it = 0; it < 9; it++){
            int c = lane + 32*it;
            float s = NEG_INF;
            if (c < C_) s = mrow[c] ? NEG_INF : row[c];
            v[it] = s;
            vmax = fmaxf(vmax, s);
        }
        #pragma unroll
        for (int off = 16; off; off >>= 1)
            vmax = fmaxf(vmax, __shfl_xor_sync(0xffffffffu, vmax, off));
        float e[9], sum = 0.f;
        #pragma unroll
        for (int it = 0; it < 9; it++){
            e[it] = __expf(v[it] - vmax);
            sum += e[it];
        }
        #pragma unroll
        for (int off = 16; off; off >>= 1)
            sum += __shfl_xor_sync(0xffffffffu, sum, off);
        float inv = 1.f / sum;
        #pragma unroll
        for (int it = 0; it < 9; it++){
            int c = lane + 32*it;
            if (c < C_) wsm[o*WPITCH + c] = f2tff(e[it] * inv);
        }
    }
    __syncthreads();

    float* base = Wt + (size_t)b * CPAD * O_ + o0;
    for (int c = wid; c < CPAD; c += 8){
        float v = (c < C_) ? wsm[lane*WPITCH + c] : 0.f;
        base[(size_t)c * O_ + lane] = v;
    }
}

// ---------------- launcher ----------------
extern "C" void kernel_launch(void* const* d_in, const int* in_sizes, int n_in,
                              void* d_out, int out_size)
{
    const float* x = nullptr;
    const float* positions = nullptr;
    const unsigned char* mask = nullptr;
    const float* heads = nullptr;
    for (int i = 0; i < n_in; i++){
        long long s = in_sizes[i];
        if      (s == (long long)B_*C_*T_) x         = (const float*)d_in[i];
        else if (s == (long long)B_*C_*2 ) positions = (const float*)d_in[i];
        else if (s == (long long)B_*C_   ) mask      = (const unsigned char*)d_in[i];
        else if (s == (long long)O_*D_   ) heads     = (const float*)d_in[i];
    }

    float *pET, *pHT, *pS, *pWt;
    cudaGetSymbolAddress((void**)&pET, g_ET);
    cudaGetSymbolAddress((void**)&pHT, g_hT);
    cudaGetSymbolAddress((void**)&pS,  g_S);
    cudaGetSymbolAddress((void**)&pWt, g_Wt);

    cudaFuncSetAttribute(gemm_tc<false>, cudaFuncAttributeMaxDynamicSharedMemorySize, GSMEM);
    cudaFuncSetAttribute(gemm_tc<true>,  cudaFuncAttributeMaxDynamicSharedMemorySize, GSMEM);

    // 1) E^T (tf32-rounded, pad cols zero)
    etgen_kernel<<<NPAD/32, 256>>>(positions);

    // 2) heads^T (tf32-rounded)
    transpose_round_kernel<<<dim3(D_/32, O_/32), dim3(32,8)>>>(heads, pHT, O_, D_);

    // 3) scores[o][bc]: M=256, N=17472, K=2048
    gemm_tc<false><<<dim3(NPAD/128, O_/128, 1), 128, GSMEM>>>(
        pHT, pET, pS,
        MTOT, D_, D_,
        O_, NPAD, MTOT,
        0, 0, 0);

    // 4) softmax -> Wt [b][cpad][o]
    softmaxT_kernel<<<dim3(O_/32, B_), 256>>>(pS, mask, pWt);

    // 5) out[b] = W[b] @ x[b]: M=256, N=2048, K=288 (273 real), batched
    gemm_tc<true><<<dim3(T_/128, O_/128, B_), 128, GSMEM>>>(
        pWt, x, (float*)d_out,
        T_, CPAD, C_,
        O_, T_, T_,
        (long long)CPAD*O_, (long long)C_*T_, (long long)O_*T_);
}

// round 7
// speedup vs baseline: 1.6857x; 1.5873x over previous
#include <cuda_runtime.h>
#include <cuda_fp16.h>
#include <math.h>
#include <cstdint>

#define B_ 64
#define C_ 273
#define T_ 2048
#define O_ 256
#define D_ 2048
#define NF 32
#define MTOT (B_*C_)      /* 17472 */
#define NPAD 17536        /* 137*128 */
#define QD (D_/2)         /* 1024 packed k-pair rows for stage 1 */
#define QC 144            /* 288/2 packed rows for stage 2 */

// ---------------- scratch (static device globals; no allocation) ----------------
__device__ __align__(16) __half2 g_EP[(size_t)QD * NPAD];  // E packed pairs [q][n] (~71.8MB)
__device__ __align__(16) __half2 g_hP[(size_t)QD * O_];    // heads packed [q][o] (1MB)
__device__ __align__(16) float   g_S [(size_t)O_ * MTOT];  // scores [o][b*273+c]
__device__ __align__(16) __half2 g_WP[(size_t)B_ * QC * O_]; // weights packed [b][q][o]

__device__ __forceinline__ uint32_t XM(int t){ return (uint32_t)((((t)&1)<<4) | (((t)&2)<<5)); }

__device__ __forceinline__ void cp_commit(){ asm volatile("cp.async.commit_group;\n"::); }
template<int N_> __device__ __forceinline__ void cp_wait(){ asm volatile("cp.async.wait_group %0;\n"::"n"(N_)); }
__device__ __forceinline__ void cpa16(void* dst, const void* src){
    unsigned d = (unsigned)__cvta_generic_to_shared(dst);
    asm volatile("cp.async.cg.shared.global [%0], [%1], 16;\n" :: "r"(d), "l"(src));
}
__device__ __forceinline__ void cpa16p(void* dst, const void* src, bool pred){
    unsigned d = (unsigned)__cvta_generic_to_shared(dst);
    int sz = pred ? 16 : 0;
    asm volatile("cp.async.cg.shared.global [%0], [%1], 16, %2;\n" :: "r"(d), "l"(src), "r"(sz));
}
// pack two f32 -> f16x2 (lo = first arg)
__device__ __forceinline__ uint32_t packh(float lo, float hi){
    uint32_t r; asm("cvt.rn.f16x2.f32 %0, %1, %2;" : "=r"(r) : "f"(hi), "f"(lo)); return r;
}

#define MMA16(acc, a0,a1,a2,a3, b0,b1) \
    asm volatile("mma.sync.aligned.m16n8k16.row.col.f32.f16.f16.f32 " \
        "{%0,%1,%2,%3}, {%4,%5,%6,%7}, {%8,%9}, {%0,%1,%2,%3};" \
        : "+f"(acc[0]), "+f"(acc[1]), "+f"(acc[2]), "+f"(acc[3]) \
        : "r"(a0), "r"(a1), "r"(a2), "r"(a3), "r"(b0), "r"(b1))

// ---------------- heads -> packed fp16 [q][o] ----------------
__global__ void hprep_kernel(const float* __restrict__ heads){
    __shared__ float2 t[32][33];
    int q0 = blockIdx.x*32, o0 = blockIdx.y*32;
    int tx = threadIdx.x, ty = threadIdx.y;   // 32 x 8
    #pragma unroll
    for (int i = 0; i < 4; i++){
        int o = o0 + ty + 8*i, q = q0 + tx;
        t[ty+8*i][tx] = *(const float2*)(heads + (size_t)o*D_ + 2*q);
    }
    __syncthreads();
    #pragma unroll
    for (int i = 0; i < 4; i++){
        int q = q0 + ty + 8*i, o = o0 + tx;
        float2 v = t[tx][ty+8*i];
        g_hP[(size_t)q*O_ + o] = __floats2half2_rn(v.x, v.y);
    }
}

// ---------------- E generator -> packed fp16 pairs [q][n] ----------------
__global__ void etgen_kernel(const float* __restrict__ positions){
    __shared__ float tc[2][NF][NF+1];
    __shared__ float ts[2][NF][NF+1];
    int n0 = blockIdx.x * 32;
    int tid = threadIdx.x;           // 256 threads
    const float twopi_w = 6.28318530717958647692f / 1.4f;
    #pragma unroll
    for (int u = 0; u < 8; u++){
        int idx   = tid + 256*u;
        int which = idx >> 10;
        int rem   = idx & 1023;
        int i     = rem >> 5;
        int r     = rem & 31;
        int n     = n0 + r;
        float c = 0.f, s = 0.f;
        if (n < MTOT){
            float p = positions[2*n + which] + 0.2f;
            sincosf((float)i * (p * twopi_w), &s, &c);
        }
        tc[which][i][r] = c;
        ts[which][i][r] = s;
    }
    __syncthreads();
    int r  = tid & 31;
    int qb = tid >> 5;
    #pragma unroll 4
    for (int q = qb; q < QD; q += 8){
        int d = 2*q;
        int m = d & 1023;
        int i = m >> 5, j = m & 31;     // j even, j+1 <= 31
        bool hi = (d >= 1024);
        float cx = tc[0][i][r],   sx = ts[0][i][r];
        float cy0 = tc[1][j][r],  sy0 = ts[1][j][r];
        float cy1 = tc[1][j+1][r],sy1 = ts[1][j+1][r];
        float v0 = hi ? (sx*cy0 + cx*sy0) : (cx*cy0 - sx*sy0);
        float v1 = hi ? (sx*cy1 + cx*sy1) : (cx*cy1 - sx*sy1);
        g_EP[(size_t)q * NPAD + n0 + r] = __floats2half2_rn(v0, v1);
    }
}

// =================================================================================
// GEMM1: S[m=o][n=bc] = sum_k heads[o][k] * E[n][k]   (M=256 full, N tiles of 128)
// A = g_hP packed [q][256], B = g_EP packed [q][NPAD]. 256 thr, 8 warps (4m x 2n),
// warp tile 64x64, k-tile = 16 (8 packed rows), 5-stage cp.async, XOR-swizzled smem.
// =================================================================================
#define G1_STG 12288            /* A 8KB + B 4KB */
#define G1_SMEM (5*G1_STG)

__global__ void __launch_bounds__(256,1) gemm1_h(
    const __half2* __restrict__ Ah, const __half2* __restrict__ Bh, float* __restrict__ S)
{
    extern __shared__ char sm[];
    int n0 = blockIdx.x*128;
    int tid = threadIdx.x, warp = tid>>5, lane = tid&31;
    int g = lane>>2, tg = lane&3;
    int wm = (warp>>1)*64, wn = (warp&1)*64;
    const uint32_t xm = XM(tg);

    float acc[4][8][4];
    #pragma unroll
    for (int mt = 0; mt < 4; mt++)
        #pragma unroll
        for (int nt = 0; nt < 8; nt++)
            #pragma unroll
            for (int e = 0; e < 4; e++) acc[mt][nt][e] = 0.f;

    const int lr = tid>>5, li = tid&31;
    auto load_stage = [&](int s, int kt){
        char* dA = sm + s*G1_STG;
        char* dB = dA + 8192;
        int q0 = kt*8;
        uint32_t xr = XM(lr&3);
        const char* srcA = (const char*)(Ah + (size_t)(q0+lr)*O_) + 32*li;
        cpa16(dA + lr*1024 + (((uint32_t)(32*li)   ) ^ xr), srcA);
        cpa16(dA + lr*1024 + (((uint32_t)(32*li+16)) ^ xr), srcA+16);
        const char* srcB = (const char*)(Bh + (size_t)(q0+lr)*NPAD + n0) + 16*li;
        cpa16(dB + lr*512 + (((uint32_t)(16*li)) ^ xr), srcB);
        cp_commit();
    };

    load_stage(0,0); load_stage(1,1); load_stage(2,2); load_stage(3,3);

    const int ktiles = D_/16;  // 128
    for (int kt = 0; kt < ktiles; kt++){
        cp_wait<3>();
        __syncthreads();
        if (kt + 4 < ktiles) load_stage((kt+4)%5, kt+4);
        else                 cp_commit();

        const char* dA = sm + (kt%5)*G1_STG;
        const char* dB = dA + 8192;
        uint32_t ab = (uint32_t)((wm + 8*g)*4);
        uint4 A0 = *(const uint4*)(dA + tg*1024     + ((ab   ) ^ xm));
        uint4 A1 = *(const uint4*)(dA + tg*1024     + ((ab+16) ^ xm));
        uint4 A2 = *(const uint4*)(dA + (tg+4)*1024 + ((ab   ) ^ xm));
        uint4 A3 = *(const uint4*)(dA + (tg+4)*1024 + ((ab+16) ^ xm));
        uint32_t bb = (uint32_t)((wn + 8*g)*4);
        uint4 B0 = *(const uint4*)(dB + tg*512      + ((bb   ) ^ xm));
        uint4 B1 = *(const uint4*)(dB + tg*512      + ((bb+16) ^ xm));
        uint4 B2 = *(const uint4*)(dB + (tg+4)*512  + ((bb   ) ^ xm));
        uint4 B3 = *(const uint4*)(dB + (tg+4)*512  + ((bb+16) ^ xm));

        uint32_t ua0[4] = {A0.x,A0.y,A0.z,A0.w};
        uint32_t ua1[4] = {A1.x,A1.y,A1.z,A1.w};
        uint32_t ua2[4] = {A2.x,A2.y,A2.z,A2.w};
        uint32_t ua3[4] = {A3.x,A3.y,A3.z,A3.w};
        uint32_t ub0[8] = {B0.x,B0.y,B0.z,B0.w,B1.x,B1.y,B1.z,B1.w};
        uint32_t ub1[8] = {B2.x,B2.y,B2.z,B2.w,B3.x,B3.y,B3.z,B3.w};

        #pragma unroll
        for (int mt = 0; mt < 4; mt++)
            #pragma unroll
            for (int nt = 0; nt < 8; nt++)
                MMA16(acc[mt][nt], ua0[mt], ua1[mt], ua2[mt], ua3[mt], ub0[nt], ub1[nt]);
    }

    // epilogue: row = wm+8g+4h+mt, 16 contiguous cols at n0+wn+16tg (guard vs MTOT)
    int cb = n0 + wn + 16*tg;
    #pragma unroll
    for (int mt = 0; mt < 4; mt++){
        #pragma unroll
        for (int h = 0; h < 2; h++){
            int row = wm + 8*g + 4*h + mt;
            float* Cr = S + (size_t)row*MTOT;
            float4 v0, v1, v2, v3;
            v0.x=acc[mt][0][2*h];   v0.y=acc[mt][1][2*h];   v0.z=acc[mt][2][2*h];   v0.w=acc[mt][3][2*h];
            v1.x=acc[mt][4][2*h];   v1.y=acc[mt][5][2*h];   v1.z=acc[mt][6][2*h];   v1.w=acc[mt][7][2*h];
            v2.x=acc[mt][0][2*h+1]; v2.y=acc[mt][1][2*h+1]; v2.z=acc[mt][2][2*h+1]; v2.w=acc[mt][3][2*h+1];
            v3.x=acc[mt][4][2*h+1]; v3.y=acc[mt][5][2*h+1]; v3.z=acc[mt][6][2*h+1]; v3.w=acc[mt][7][2*h+1];
            if (cb      < MTOT) *(float4*)(Cr + cb     ) = v0;
            if (cb + 4  < MTOT) *(float4*)(Cr + cb + 4 ) = v1;
            if (cb + 8  < MTOT) *(float4*)(Cr + cb + 8 ) = v2;
            if (cb + 12 < MTOT) *(float4*)(Cr + cb + 12) = v3;
        }
    }
}

// =================================================================================
// GEMM2: out[b][m=o][n=t] = sum_c W[b][o][c] * x[b][c][t]  (M=256 full, N tiles 128)
// A = g_WP packed fp16 [b][q][256]; B = x fp32 [c][t] staged raw, packed in-register.
// =================================================================================
#define G2_STG 16384            /* A 8KB + B 8KB */
#define G2_SMEM (5*G2_STG)

__global__ void __launch_bounds__(256,1) gemm2_h(
    const __half2* __restrict__ WP, const float* __restrict__ xg, float* __restrict__ out)
{
    extern __shared__ char sm[];
    int b = blockIdx.z;
    const __half2* Ah = WP + (size_t)b*QC*O_;
    const float*   Bx = xg + (size_t)b*C_*T_;
    float*         C  = out + (size_t)b*O_*T_;

    int n0 = blockIdx.x*128;
    int tid = threadIdx.x, warp = tid>>5, lane = tid&31;
    int g = lane>>2, tg = lane&3;
    int wm = (warp>>1)*64, wn = (warp&1)*64;
    const uint32_t xm = XM(tg);

    float acc[4][8][4];
    #pragma unroll
    for (int mt = 0; mt < 4; mt++)
        #pragma unroll
        for (int nt = 0; nt < 8; nt++)
            #pragma unroll
            for (int e = 0; e < 4; e++) acc[mt][nt][e] = 0.f;

    const int lrA = tid>>5, liA = tid&31;
    const int lrB = tid>>4, liB = tid&15;
    auto load_stage = [&](int s, int kt){
        char* dA = sm + s*G2_STG;
        char* dB = dA + 8192;
        int q0 = kt*8, k0 = kt*16;
        uint32_t xrA = XM(lrA&3);
        const char* srcA = (const char*)(Ah + (size_t)(q0+lrA)*O_) + 32*liA;
        cpa16(dA + lrA*1024 + (((uint32_t)(32*liA)   ) ^ xrA), srcA);
        cpa16(dA + lrA*1024 + (((uint32_t)(32*liA+16)) ^ xrA), srcA+16);
        uint32_t xrB = XM((lrB>>1)&3);
        bool pr = (k0 + lrB) < C_;
        const char* srcB = (const char*)(Bx + (size_t)(k0+lrB)*T_ + n0);
        cpa16p(dB + lrB*512 + (((uint32_t)(16*liB    )) ^ xrB), srcB + 16*liB,       pr);
        cpa16p(dB + lrB*512 + (((uint32_t)(16*liB+256)) ^ xrB), srcB + 16*liB + 256, pr);
        cp_commit();
    };

    load_stage(0,0); load_stage(1,1); load_stage(2,2); load_stage(3,3);

    const int ktiles = 2*QC/16;  // 18
    for (int kt = 0; kt < ktiles; kt++){
        cp_wait<3>();
        __syncthreads();
        if (kt + 4 < ktiles) load_stage((kt+4)%5, kt+4);
        else                 cp_commit();

        const char* dA = sm + (kt%5)*G2_STG;
        const char* dB = dA + 8192;
        uint32_t ab = (uint32_t)((wm + 8*g)*4);
        uint4 A0 = *(const uint4*)(dA + tg*1024     + ((ab   ) ^ xm));
        uint4 A1 = *(const uint4*)(dA + tg*1024     + ((ab+16) ^ xm));
        uint4 A2 = *(const uint4*)(dA + (tg+4)*1024 + ((ab   ) ^ xm));
        uint4 A3 = *(const uint4*)(dA + (tg+4)*1024 + ((ab+16) ^ xm));

        uint32_t bb = (uint32_t)((wn + 8*g)*4);
        uint32_t c0 = (bb   ) ^ xm;
        uint32_t c1 = (bb+16) ^ xm;
        float4 e0 = *(const float4*)(dB + (2*tg  )*512 + c0);
        float4 e1 = *(const float4*)(dB + (2*tg  )*512 + c1);
        float4 o0 = *(const float4*)(dB + (2*tg+1)*512 + c0);
        float4 o1 = *(const float4*)(dB + (2*tg+1)*512 + c1);
        float4 E0 = *(const float4*)(dB + (2*tg+8)*512 + c0);
        float4 E1 = *(const float4*)(dB + (2*tg+8)*512 + c1);
        float4 O0 = *(const float4*)(dB + (2*tg+9)*512 + c0);
        float4 O1 = *(const float4*)(dB + (2*tg+9)*512 + c1);

        uint32_t ua0[4] = {A0.x,A0.y,A0.z,A0.w};
        uint32_t ua1[4] = {A1.x,A1.y,A1.z,A1.w};
        uint32_t ua2[4] = {A2.x,A2.y,A2.z,A2.w};
        uint32_t ua3[4] = {A3.x,A3.y,A3.z,A3.w};
        uint32_t ub0[8], ub1[8];
        ub0[0]=packh(e0.x,o0.x); ub0[1]=packh(e0.y,o0.y); ub0[2]=packh(e0.z,o0.z); ub0[3]=packh(e0.w,o0.w);
        ub0[4]=packh(e1.x,o1.x); ub0[5]=packh(e1.y,o1.y); ub0[6]=packh(e1.z,o1.z); ub0[7]=packh(e1.w,o1.w);
        ub1[0]=packh(E0.x,O0.x); ub1[1]=packh(E0.y,O0.y); ub1[2]=packh(E0.z,O0.z); ub1[3]=packh(E0.w,O0.w);
        ub1[4]=packh(E1.x,O1.x); ub1[5]=packh(E1.y,O1.y); ub1[6]=packh(E1.z,O1.z); ub1[7]=packh(E1.w,O1.w);

        #pragma unroll
        for (int mt = 0; mt < 4; mt++)
            #pragma unroll
            for (int nt = 0; nt < 8; nt++)
                MMA16(acc[mt][nt], ua0[mt], ua1[mt], ua2[mt], ua3[mt], ub0[nt], ub1[nt]);
    }

    int cb = n0 + wn + 16*tg;   // always in-bounds (T_ multiple of 128)
    #pragma unroll
    for (int mt = 0; mt < 4; mt++){
        #pragma unroll
        for (int h = 0; h < 2; h++){
            int row = wm + 8*g + 4*h + mt;
            float* Cr = C + (size_t)row*T_;
            float4 v0, v1, v2, v3;
            v0.x=acc[mt][0][2*h];   v0.y=acc[mt][1][2*h];   v0.z=acc[mt][2][2*h];   v0.w=acc[mt][3][2*h];
            v1.x=acc[mt][4][2*h];   v1.y=acc[mt][5][2*h];   v1.z=acc[mt][6][2*h];   v1.w=acc[mt][7][2*h];
            v2.x=acc[mt][0][2*h+1]; v2.y=acc[mt][1][2*h+1]; v2.z=acc[mt][2][2*h+1]; v2.w=acc[mt][3][2*h+1];
            v3.x=acc[mt][4][2*h+1]; v3.y=acc[mt][5][2*h+1]; v3.z=acc[mt][6][2*h+1]; v3.w=acc[mt][7][2*h+1];
            *(float4*)(Cr + cb     ) = v0;
            *(float4*)(Cr + cb + 4 ) = v1;
            *(float4*)(Cr + cb + 8 ) = v2;
            *(float4*)(Cr + cb + 12) = v3;
        }
    }
}

// ---------------- softmax over C, writing packed fp16 W^T directly ----------------
#define WPITCH 277
__global__ void __launch_bounds__(256) softmaxT_kernel(
    const float* __restrict__ S, const unsigned char* __restrict__ mask,
    __half2* __restrict__ WP)
{
    __shared__ float wsm[32*WPITCH];
    const float NEG_INF = __int_as_float(0xff800000);
    int o0 = blockIdx.x * 32;
    int b  = blockIdx.y;
    int tid = threadIdx.x, wid = tid >> 5, lane = tid & 31;
    const unsigned char* mrow = mask + (size_t)b * C_;

    #pragma unroll
    for (int p = 0; p < 4; p++){
        int o = 4*wid + p;
        const float* row = S + (size_t)(o0 + o) * MTOT + (size_t)b * C_;
        float v[9];
        float vmax = NEG_INF;
        #pragma unroll
        for (int it = 0; it < 9; it++){
            int c = lane + 32*it;
            float s = NEG_INF;
            if (c < C_) s = mrow[c] ? NEG_INF : row[c];
            v[it] = s;
            vmax = fmaxf(vmax, s);
        }
        #pragma unroll
        for (int off = 16; off; off >>= 1)
            vmax = fmaxf(vmax, __shfl_xor_sync(0xffffffffu, vmax, off));
        float e[9], sum = 0.f;
        #pragma unroll
        for (int it = 0; it < 9; it++){
            e[it] = __expf(v[it] - vmax);
            sum += e[it];
        }
        #pragma unroll
        for (int off = 16; off; off >>= 1)
            sum += __shfl_xor_sync(0xffffffffu, sum, off);
        float inv = 1.f / sum;
        #pragma unroll
        for (int it = 0; it < 9; it++){
            int c = lane + 32*it;
            if (c < C_) wsm[o*WPITCH + c] = e[it] * inv;
        }
    }
    __syncthreads();

    // WP[b][q][o0+lane] = half2(W[o][2q], W[o][2q+1]) with o = o0+lane
    __half2* base = WP + (size_t)b * QC * O_ + o0;
    for (int q = wid; q < QC; q += 8){
        int c0 = 2*q, c1 = 2*q + 1;
        float w0 = (c0 < C_) ? wsm[lane*WPITCH + c0] : 0.f;
        float w1 = (c1 < C_) ? wsm[lane*WPITCH + c1] : 0.f;
        base[(size_t)q * O_ + lane] = __floats2half2_rn(w0, w1);
    }
}

// ---------------- launcher ----------------
extern "C" void kernel_launch(void* const* d_in, const int* in_sizes, int n_in,
                              void* d_out, int out_size)
{
    const float* x = nullptr;
    const float* positions = nullptr;
    const unsigned char* mask = nullptr;
    const float* heads = nullptr;
    for (int i = 0; i < n_in; i++){
        long long s = in_sizes[i];
        if      (s == (long long)B_*C_*T_) x         = (const float*)d_in[i];
        else if (s == (long long)B_*C_*2 ) positions = (const float*)d_in[i];
        else if (s == (long long)B_*C_   ) mask      = (const unsigned char*)d_in[i];
        else if (s == (long long)O_*D_   ) heads     = (const float*)d_in[i];
    }

    __half2 *pEP, *pHP, *pWP;
    float *pS;
    cudaGetSymbolAddress((void**)&pEP, g_EP);
    cudaGetSymbolAddress((void**)&pHP, g_hP);
    cudaGetSymbolAddress((void**)&pS,  g_S);
    cudaGetSymbolAddress((void**)&pWP, g_WP);

    cudaFuncSetAttribute(gemm1_h, cudaFuncAttributeMaxDynamicSharedMemorySize, G1_SMEM);
    cudaFuncSetAttribute(gemm2_h, cudaFuncAttributeMaxDynamicSharedMemorySize, G2_SMEM);

    // 1) heads -> packed fp16 [q][o]
    hprep_kernel<<<dim3(QD/32, O_/32), dim3(32,8)>>>(heads);

    // 2) E -> packed fp16 pairs [q][n] (pad cols zero)
    etgen_kernel<<<NPAD/32, 256>>>(positions);

    // 3) scores: M=256(full), N=17472, K=2048   — 137 CTAs, single wave
    gemm1_h<<<dim3(NPAD/128, 1, 1), 256, G1_SMEM>>>(pHP, pEP, pS);

    // 4) softmax -> packed W^T [b][q][o]
    softmaxT_kernel<<<dim3(O_/32, B_), 256>>>(pS, mask, pWP);

    // 5) out[b] = W[b] @ x[b]: M=256(full), N=2048, K=288 (273 real), batched
    gemm2_h<<<dim3(T_/128, 1, B_), 256, G2_SMEM>>>(pWP, x, (float*)d_out);
}